// round 1
// baseline (speedup 1.0000x reference)
#include <cuda_runtime.h>
#include <cuda_bf16.h>
#include <cstdint>

// ESN collapsed op: out[bt, r] = (1 - lr) * tanh( sum_i x[bt,i] * w[r,i] )
// B*T = 1,048,576 rows, I = 8, R = 128. Store-bandwidth bound (~537MB out).

__device__ __forceinline__ unsigned long long pk2(float lo, float hi) {
    unsigned long long r;
    asm("mov.b64 %0, {%1, %2};" : "=l"(r) : "f"(lo), "f"(hi));
    return r;
}
__device__ __forceinline__ void upk2(float& lo, float& hi, unsigned long long v) {
    asm("mov.b64 {%0, %1}, %2;" : "=f"(lo), "=f"(hi) : "l"(v));
}
__device__ __forceinline__ unsigned long long mul2(unsigned long long a, unsigned long long b) {
    unsigned long long r;
    asm("mul.rn.f32x2 %0, %1, %2;" : "=l"(r) : "l"(a), "l"(b));
    return r;
}
__device__ __forceinline__ unsigned long long fma2(unsigned long long a, unsigned long long b,
                                                   unsigned long long c) {
    unsigned long long r;
    asm("fma.rn.f32x2 %0, %1, %2, %3;" : "=l"(r) : "l"(a), "l"(b), "l"(c));
    return r;
}
__device__ __forceinline__ float tanh_ap(float x) {
    float y;
    asm("tanh.approx.f32 %0, %1;" : "=f"(y) : "f"(x));
    return y;
}

__global__ void __launch_bounds__(256) ESN_11390253269642_kernel(
    const float* __restrict__ x,     // [BT, 8]
    const float* __restrict__ w,     // [128, 8]
    const float* __restrict__ lrp,   // [1]
    float* __restrict__ out,         // [BT, 128]
    int bt_total)
{
    const int lane = threadIdx.x & 31;
    const int gwarp = blockIdx.x * (blockDim.x >> 5) + (threadIdx.x >> 5);
    const int nwarp = gridDim.x * (blockDim.x >> 5);
    const float s = 1.0f - __ldg(lrp);

    // Preload the 4 w_in rows this lane owns (r = 4*lane + q), packed f32x2.
    unsigned long long wr[4][4];
#pragma unroll
    for (int q = 0; q < 4; q++) {
        const float4* p = reinterpret_cast<const float4*>(w + (lane * 4 + q) * 8);
        float4 a = __ldg(p);
        float4 b = __ldg(p + 1);
        wr[q][0] = pk2(a.x, a.y);
        wr[q][1] = pk2(a.z, a.w);
        wr[q][2] = pk2(b.x, b.y);
        wr[q][3] = pk2(b.z, b.w);
    }

    for (int bt = gwarp; bt < bt_total; bt += nwarp) {
        const float4* xp = reinterpret_cast<const float4*>(x + (size_t)bt * 8);
        float4 xa = __ldg(xp);       // broadcast: all lanes same address
        float4 xb = __ldg(xp + 1);
        unsigned long long x0 = pk2(xa.x, xa.y);
        unsigned long long x1 = pk2(xa.z, xa.w);
        unsigned long long x2 = pk2(xb.x, xb.y);
        unsigned long long x3 = pk2(xb.z, xb.w);

        float4 o;
        float* op = &o.x;
#pragma unroll
        for (int q = 0; q < 4; q++) {
            unsigned long long acc = mul2(wr[q][0], x0);
            acc = fma2(wr[q][1], x1, acc);
            acc = fma2(wr[q][2], x2, acc);
            acc = fma2(wr[q][3], x3, acc);
            float lo, hi;
            upk2(lo, hi, acc);
            op[q] = s * tanh_ap(lo + hi);
        }
        // lane-contiguous float4 store: 512B per warp, fully coalesced
        reinterpret_cast<float4*>(out + (size_t)bt * 128)[lane] = o;
    }
}

extern "C" void kernel_launch(void* const* d_in, const int* in_sizes, int n_in,
                              void* d_out, int out_size)
{
    const float* x   = (const float*)d_in[0];   // [B, T, I] fp32
    const float* w   = (const float*)d_in[1];   // [R, I] fp32
    // d_in[2] = d, unused (contributes exactly 0 in the reference)
    const float* lr  = (const float*)d_in[3];   // [1] fp32
    float* out = (float*)d_out;

    const int bt_total = in_sizes[0] / 8;       // B*T rows

    // Grid-stride: enough warps to saturate, enough iters/warp to amortize
    // the per-warp w_in preload.
    int blocks = (bt_total + 2047) / 2048;      // ~32 bt per warp at full size
    if (blocks < 1) blocks = 1;
    if (blocks > 4096) blocks = 4096;
    ESN_11390253269642_kernel<<<blocks, 256>>>(x, w, lr, out, bt_total);
}

// round 2
// speedup vs baseline: 1.5673x; 1.5673x over previous
#include <cuda_runtime.h>
#include <cuda_bf16.h>
#include <cstdint>

// ESN collapsed op: out[bt, r] = (1 - lr) * tanh( sum_i x[bt,i] * w[r,i] )
// B*T = 1,048,576 rows, I = 8, R = 128. Store-stream bound (~537MB out).
// One warp per group of 4 consecutive bt rows; lane owns r in [4*lane, 4*lane+4).

__device__ __forceinline__ unsigned long long pk2(float lo, float hi) {
    unsigned long long r;
    asm("mov.b64 %0, {%1, %2};" : "=l"(r) : "f"(lo), "f"(hi));
    return r;
}
__device__ __forceinline__ void upk2(float& lo, float& hi, unsigned long long v) {
    asm("mov.b64 {%0, %1}, %2;" : "=f"(lo), "=f"(hi) : "l"(v));
}
__device__ __forceinline__ unsigned long long mul2(unsigned long long a, unsigned long long b) {
    unsigned long long r;
    asm("mul.rn.f32x2 %0, %1, %2;" : "=l"(r) : "l"(a), "l"(b));
    return r;
}
__device__ __forceinline__ unsigned long long fma2(unsigned long long a, unsigned long long b,
                                                   unsigned long long c) {
    unsigned long long r;
    asm("fma.rn.f32x2 %0, %1, %2, %3;" : "=l"(r) : "l"(a), "l"(b), "l"(c));
    return r;
}
__device__ __forceinline__ float tanh_ap(float x) {
    float y;
    asm("tanh.approx.f32 %0, %1;" : "=f"(y) : "f"(x));
    return y;
}

__global__ void __launch_bounds__(256, 3) ESN_11390253269642_kernel(
    const float* __restrict__ x,     // [BT, 8]
    const float* __restrict__ w,     // [128, 8]
    const float* __restrict__ lrp,   // [1]
    float* __restrict__ out,         // [BT, 128]
    int bt_total)
{
    const int lane = threadIdx.x & 31;
    const int gwarp = blockIdx.x * (blockDim.x >> 5) + (threadIdx.x >> 5);
    const int nwarp = gridDim.x * (blockDim.x >> 5);
    const float s = 1.0f - __ldg(lrp);

    // Preload the 4 w_in rows this lane owns (r = 4*lane + q), packed f32x2.
    unsigned long long wr[4][4];
#pragma unroll
    for (int q = 0; q < 4; q++) {
        const float4* p = reinterpret_cast<const float4*>(w + (lane * 4 + q) * 8);
        float4 a = __ldg(p);
        float4 b = __ldg(p + 1);
        wr[q][0] = pk2(a.x, a.y);
        wr[q][1] = pk2(a.z, a.w);
        wr[q][2] = pk2(b.x, b.y);
        wr[q][3] = pk2(b.z, b.w);
    }

    const int ROWS = 4;
    // main loop: 4 consecutive rows per warp-iteration, loads front-batched
    int bt = gwarp * ROWS;
    for (; bt + ROWS <= bt_total; bt += nwarp * ROWS) {
        const float4* xp = reinterpret_cast<const float4*>(x + (size_t)bt * 8);
        float4 xa[ROWS], xb[ROWS];
#pragma unroll
        for (int j = 0; j < ROWS; j++) {
            xa[j] = __ldcs(xp + 2 * j);       // broadcast loads, all independent
            xb[j] = __ldcs(xp + 2 * j + 1);
        }
#pragma unroll
        for (int j = 0; j < ROWS; j++) {
            unsigned long long x0 = pk2(xa[j].x, xa[j].y);
            unsigned long long x1 = pk2(xa[j].z, xa[j].w);
            unsigned long long x2 = pk2(xb[j].x, xb[j].y);
            unsigned long long x3 = pk2(xb[j].z, xb[j].w);
            float4 o;
            float* op = &o.x;
#pragma unroll
            for (int q = 0; q < 4; q++) {
                unsigned long long acc = mul2(wr[q][0], x0);
                acc = fma2(wr[q][1], x1, acc);
                acc = fma2(wr[q][2], x2, acc);
                acc = fma2(wr[q][3], x3, acc);
                float lo, hi;
                upk2(lo, hi, acc);
                op[q] = s * tanh_ap(lo + hi);
            }
            __stcs(reinterpret_cast<float4*>(out + (size_t)(bt + j) * 128) + lane, o);
        }
    }
    // tail (bt_total not multiple of 4*nwarp handled by strided singles)
    for (; bt < bt_total; bt++) {
        const float4* xp = reinterpret_cast<const float4*>(x + (size_t)bt * 8);
        float4 xa = __ldcs(xp);
        float4 xb = __ldcs(xp + 1);
        unsigned long long x0 = pk2(xa.x, xa.y);
        unsigned long long x1 = pk2(xa.z, xa.w);
        unsigned long long x2 = pk2(xb.x, xb.y);
        unsigned long long x3 = pk2(xb.z, xb.w);
        float4 o;
        float* op = &o.x;
#pragma unroll
        for (int q = 0; q < 4; q++) {
            unsigned long long acc = mul2(wr[q][0], x0);
            acc = fma2(wr[q][1], x1, acc);
            acc = fma2(wr[q][2], x2, acc);
            acc = fma2(wr[q][3], x3, acc);
            float lo, hi;
            upk2(lo, hi, acc);
            op[q] = s * tanh_ap(lo + hi);
        }
        __stcs(reinterpret_cast<float4*>(out + (size_t)bt * 128) + lane, o);
    }
}

extern "C" void kernel_launch(void* const* d_in, const int* in_sizes, int n_in,
                              void* d_out, int out_size)
{
    const float* x   = (const float*)d_in[0];   // [B, T, I] fp32
    const float* w   = (const float*)d_in[1];   // [R, I] fp32
    // d_in[2] = d, unused (contributes exactly 0 in the reference)
    const float* lr  = (const float*)d_in[3];   // [1] fp32
    float* out = (float*)d_out;

    const int bt_total = in_sizes[0] / 8;       // B*T rows

    // Persistent grid: 3 blocks/SM x 148 SMs = one full wave, grid-stride loop.
    int blocks = 444;
    long long need = ((long long)bt_total + 31) / 32;  // warps if 4 rows x >=1 iter
    if (need < (long long)blocks * 8) blocks = (int)((need + 7) / 8);
    if (blocks < 1) blocks = 1;
    ESN_11390253269642_kernel<<<blocks, 256>>>(x, w, lr, out, bt_total);
}

// round 3
// speedup vs baseline: 1.7191x; 1.0969x over previous
#include <cuda_runtime.h>
#include <cuda_bf16.h>
#include <cstdint>

// ESN collapsed op: out[bt, r] = (1 - lr) * tanh( sum_i x[bt,i] * w[r,i] )
// B*T = 1,048,576 rows, I = 8, R = 128. Store-stream bound (~537MB out).
// cp.async double-buffered x staging; lane owns r in [4*lane, 4*lane+4).

__device__ __forceinline__ unsigned long long pk2(float lo, float hi) {
    unsigned long long r;
    asm("mov.b64 %0, {%1, %2};" : "=l"(r) : "f"(lo), "f"(hi));
    return r;
}
__device__ __forceinline__ void upk2(float& lo, float& hi, unsigned long long v) {
    asm("mov.b64 {%0, %1}, %2;" : "=f"(lo), "=f"(hi) : "l"(v));
}
__device__ __forceinline__ unsigned long long mul2(unsigned long long a, unsigned long long b) {
    unsigned long long r;
    asm("mul.rn.f32x2 %0, %1, %2;" : "=l"(r) : "l"(a), "l"(b));
    return r;
}
__device__ __forceinline__ unsigned long long fma2(unsigned long long a, unsigned long long b,
                                                   unsigned long long c) {
    unsigned long long r;
    asm("fma.rn.f32x2 %0, %1, %2, %3;" : "=l"(r) : "l"(a), "l"(b), "l"(c));
    return r;
}
__device__ __forceinline__ float tanh_ap(float x) {
    float y;
    asm("tanh.approx.f32 %0, %1;" : "=f"(y) : "f"(x));
    return y;
}

static constexpr int TILE = 64;            // rows per stage per block
static constexpr int TILE_F = TILE * 8;    // floats per stage (512)

__global__ void __launch_bounds__(256, 4) ESN_11390253269642_kernel(
    const float* __restrict__ x,     // [BT, 8]
    const float* __restrict__ w,     // [128, 8]
    const float* __restrict__ lrp,   // [1]
    float* __restrict__ out,         // [BT, 128]
    int bt_total)
{
    __shared__ float xs[2][TILE_F];

    const int tid  = threadIdx.x;
    const int lane = tid & 31;
    const int wid  = tid >> 5;           // 0..7
    const float s = 1.0f - __ldg(lrp);

    // Preload the 4 w_in rows this lane owns (r = 4*lane + q), packed f32x2.
    unsigned long long wr[4][4];
#pragma unroll
    for (int q = 0; q < 4; q++) {
        const float4* p = reinterpret_cast<const float4*>(w + (lane * 4 + q) * 8);
        float4 a = __ldg(p);
        float4 b = __ldg(p + 1);
        wr[q][0] = pk2(a.x, a.y);
        wr[q][1] = pk2(a.z, a.w);
        wr[q][2] = pk2(b.x, b.y);
        wr[q][3] = pk2(b.z, b.w);
    }

    const long long total_f = (long long)bt_total * 8;
    const int ntiles = (bt_total + TILE - 1) / TILE;

    // cp.async issue of one tile (128 x 16B, threads 0..127)
    auto issue_tile = [&](int tile, int buf) {
        if (tid < 128) {
            long long off = (long long)tile * TILE_F + tid * 4;
            if (off < total_f) {
                uint32_t dst = (uint32_t)__cvta_generic_to_shared(&xs[buf][tid * 4]);
                const float* src = x + off;
                asm volatile("cp.async.ca.shared.global [%0], [%1], 16;"
                             :: "r"(dst), "l"(src));
            }
        }
    };

    int tile = blockIdx.x;
    int buf = 0;
    if (tile < ntiles) issue_tile(tile, 0);
    asm volatile("cp.async.commit_group;");

    for (; tile < ntiles; tile += gridDim.x) {
        int next = tile + gridDim.x;
        if (next < ntiles) issue_tile(next, buf ^ 1);
        asm volatile("cp.async.commit_group;");
        asm volatile("cp.async.wait_group 1;");
        __syncthreads();                 // tile's data visible to all warps

        // this warp computes rows [wid*8, wid*8+8) of the tile
        const int rbase = tile * TILE + wid * 8;
        const float* xb_s = &xs[buf][wid * 8 * 8];
#pragma unroll
        for (int j = 0; j < 8; j++) {
            int row = rbase + j;
            if (row >= bt_total) break;
            float4 xa = *reinterpret_cast<const float4*>(xb_s + j * 8);      // LDS.128 bcast
            float4 xbv = *reinterpret_cast<const float4*>(xb_s + j * 8 + 4);
            unsigned long long x0 = pk2(xa.x, xa.y);
            unsigned long long x1 = pk2(xa.z, xa.w);
            unsigned long long x2 = pk2(xbv.x, xbv.y);
            unsigned long long x3 = pk2(xbv.z, xbv.w);
            float4 o;
            float* op = &o.x;
#pragma unroll
            for (int q = 0; q < 4; q++) {
                unsigned long long acc = mul2(wr[q][0], x0);
                acc = fma2(wr[q][1], x1, acc);
                acc = fma2(wr[q][2], x2, acc);
                acc = fma2(wr[q][3], x3, acc);
                float lo, hi;
                upk2(lo, hi, acc);
                op[q] = s * tanh_ap(lo + hi);
            }
            __stcs(reinterpret_cast<float4*>(out + (size_t)row * 128) + lane, o);
        }
        __syncthreads();                 // done reading buf before it is overwritten
        buf ^= 1;
    }
}

extern "C" void kernel_launch(void* const* d_in, const int* in_sizes, int n_in,
                              void* d_out, int out_size)
{
    const float* x   = (const float*)d_in[0];   // [B, T, I] fp32
    const float* w   = (const float*)d_in[1];   // [R, I] fp32
    // d_in[2] = d, unused (contributes exactly 0 in the reference)
    const float* lr  = (const float*)d_in[3];   // [1] fp32
    float* out = (float*)d_out;

    const int bt_total = in_sizes[0] / 8;       // B*T rows

    // Persistent grid: 4 blocks/SM x 148 SMs, grid-stride over 64-row tiles.
    int ntiles = (bt_total + TILE - 1) / TILE;
    int blocks = 592;
    if (blocks > ntiles) blocks = ntiles;
    if (blocks < 1) blocks = 1;
    ESN_11390253269642_kernel<<<blocks, 256>>>(x, w, lr, out, bt_total);
}

// round 4
// speedup vs baseline: 1.9290x; 1.1221x over previous
#include <cuda_runtime.h>
#include <cuda_bf16.h>
#include <cstdint>

// ESN collapsed op: out[bt, r] = (1 - lr) * tanh( sum_i x[bt,i] * w[r,i] )
// B*T = 1,048,576 rows, I = 8, R = 128. Store-stream bound (~537MB out).
// cp.async double-buffered x staging. Each warp handles HALF a row
// (64 r-values, 2 per lane) -> small reg footprint -> 6 blocks/SM.

__device__ __forceinline__ unsigned long long pk2(float lo, float hi) {
    unsigned long long r;
    asm("mov.b64 %0, {%1, %2};" : "=l"(r) : "f"(lo), "f"(hi));
    return r;
}
__device__ __forceinline__ void upk2(float& lo, float& hi, unsigned long long v) {
    asm("mov.b64 {%0, %1}, %2;" : "=f"(lo), "=f"(hi) : "l"(v));
}
__device__ __forceinline__ unsigned long long mul2(unsigned long long a, unsigned long long b) {
    unsigned long long r;
    asm("mul.rn.f32x2 %0, %1, %2;" : "=l"(r) : "l"(a), "l"(b));
    return r;
}
__device__ __forceinline__ unsigned long long fma2(unsigned long long a, unsigned long long b,
                                                   unsigned long long c) {
    unsigned long long r;
    asm("fma.rn.f32x2 %0, %1, %2, %3;" : "=l"(r) : "l"(a), "l"(b), "l"(c));
    return r;
}
__device__ __forceinline__ float tanh_ap(float x) {
    float y;
    asm("tanh.approx.f32 %0, %1;" : "=f"(y) : "f"(x));
    return y;
}

static constexpr int TILE = 128;           // rows per stage per block
static constexpr int TILE_F = TILE * 8;    // floats per stage (1024 = 4KB)

__global__ void __launch_bounds__(256, 6) ESN_11390253269642_kernel(
    const float* __restrict__ x,     // [BT, 8]
    const float* __restrict__ w,     // [128, 8]
    const float* __restrict__ lrp,   // [1]
    float* __restrict__ out,         // [BT, 128]
    int bt_total)
{
    __shared__ float xs[2][TILE_F];

    const int tid  = threadIdx.x;
    const int lane = tid & 31;
    const int wid  = tid >> 5;           // 0..7
    const int half = wid & 1;            // which 64-wide half of the row
    const int wrow = wid >> 1;           // 0..3: row offset within stride-4 groups
    const float s = 1.0f - __ldg(lrp);

    // This lane owns r0 = half*64 + lane*2 and r1 = r0+1.
    // w rows packed as f32x2 pairs (one-time cost).
    unsigned long long w0[4], w1[4];
    {
        const int r0 = half * 64 + lane * 2;
        const float4* p0 = reinterpret_cast<const float4*>(w + r0 * 8);
        float4 a = __ldg(p0), b = __ldg(p0 + 1);
        w0[0] = pk2(a.x, a.y); w0[1] = pk2(a.z, a.w);
        w0[2] = pk2(b.x, b.y); w0[3] = pk2(b.z, b.w);
        const float4* p1 = reinterpret_cast<const float4*>(w + (r0 + 1) * 8);
        a = __ldg(p1); b = __ldg(p1 + 1);
        w1[0] = pk2(a.x, a.y); w1[1] = pk2(a.z, a.w);
        w1[2] = pk2(b.x, b.y); w1[3] = pk2(b.z, b.w);
    }

    const long long total_f = (long long)bt_total * 8;
    const int ntiles = (bt_total + TILE - 1) / TILE;

    // cp.async: 256 threads x 16B = 4KB = one full tile
    auto issue_tile = [&](int tile, int buf) {
        long long off = (long long)tile * TILE_F + tid * 4;
        if (off < total_f) {
            uint32_t dst = (uint32_t)__cvta_generic_to_shared(&xs[buf][tid * 4]);
            const float* src = x + off;
            asm volatile("cp.async.ca.shared.global [%0], [%1], 16;"
                         :: "r"(dst), "l"(src));
        }
    };

    int tile = blockIdx.x;
    int buf = 0;
    if (tile < ntiles) issue_tile(tile, 0);
    asm volatile("cp.async.commit_group;");

    for (; tile < ntiles; tile += gridDim.x) {
        int next = tile + gridDim.x;
        if (next < ntiles) issue_tile(next, buf ^ 1);
        asm volatile("cp.async.commit_group;");
        asm volatile("cp.async.wait_group 1;");
        __syncthreads();

        const int rowlim = bt_total - tile * TILE;   // rows valid in this tile
        // warp handles rows wrow, wrow+4, ..., wrow+124 (32 units), half 'half'
        uint32_t xaddr = (uint32_t)__cvta_generic_to_shared(&xs[buf][wrow * 8]);
        float* obase = out + (size_t)(tile * TILE + wrow) * 128 + half * 64 + lane * 2;
#pragma unroll 4
        for (int j = 0; j < 32; j++) {
            int rit = wrow + j * 4;
            if (rit >= rowlim) break;
            unsigned long long xv0, xv1, xv2, xv3;
            uint32_t a = xaddr + (uint32_t)(j * 4 * 32);  // 4 rows * 32B per j-step
            asm volatile("ld.shared.v2.u64 {%0, %1}, [%2];"
                         : "=l"(xv0), "=l"(xv1) : "r"(a));
            asm volatile("ld.shared.v2.u64 {%0, %1}, [%2];"
                         : "=l"(xv2), "=l"(xv3) : "r"(a + 16));

            unsigned long long acc0 = mul2(w0[0], xv0);
            unsigned long long acc1 = mul2(w1[0], xv0);
            acc0 = fma2(w0[1], xv1, acc0);
            acc1 = fma2(w1[1], xv1, acc1);
            acc0 = fma2(w0[2], xv2, acc0);
            acc1 = fma2(w1[2], xv2, acc1);
            acc0 = fma2(w0[3], xv3, acc0);
            acc1 = fma2(w1[3], xv3, acc1);

            float lo0, hi0, lo1, hi1;
            upk2(lo0, hi0, acc0);
            upk2(lo1, hi1, acc1);
            float2 o;
            o.x = s * tanh_ap(lo0 + hi0);
            o.y = s * tanh_ap(lo1 + hi1);
            __stcs(reinterpret_cast<float2*>(obase + (size_t)j * 4 * 128), o);
        }
        __syncthreads();
        buf ^= 1;
    }
}

extern "C" void kernel_launch(void* const* d_in, const int* in_sizes, int n_in,
                              void* d_out, int out_size)
{
    const float* x   = (const float*)d_in[0];   // [B, T, I] fp32
    const float* w   = (const float*)d_in[1];   // [R, I] fp32
    // d_in[2] = d, unused (contributes exactly 0 in the reference)
    const float* lr  = (const float*)d_in[3];   // [1] fp32
    float* out = (float*)d_out;

    const int bt_total = in_sizes[0] / 8;       // B*T rows

    int ntiles = (bt_total + TILE - 1) / TILE;
    int blocks = 888;                            // 6 blocks/SM x 148 SMs
    if (blocks > ntiles) blocks = ntiles;
    if (blocks < 1) blocks = 1;
    ESN_11390253269642_kernel<<<blocks, 256>>>(x, w, lr, out, bt_total);
}